// round 3
// baseline (speedup 1.0000x reference)
#include <cuda_runtime.h>

// Problem constants
#define S_LEN  2048
#define DM     1024
#define NH     16
#define DKH    64
#define BATCH  2
#define NTOK   (BATCH * S_LEN)   // 4096

// Scratch (allocation-free rule: __device__ globals)
__device__ float g_Qp[(size_t)NTOK * DM];    // projected Q  [B*S, D]
__device__ float g_Kp[(size_t)NTOK * DKH];   // projected K  [B*S, d_k]
__device__ float g_Vp[(size_t)NTOK * DKH];   // projected V  [B*S, d_k]
__device__ float g_Xo[(size_t)NTOK * DM];    // attention out [B*S, D]

// ---------------------------------------------------------------------------
// C[M,N] = A[M,K] @ B[K,N] + bias[N]
// 64x64 tile, BK=16, 256 threads, 4x4 micro-tile per thread.
// Requires M%64==0, N%64==0, K%16==0 (true for all uses here).
// ---------------------------------------------------------------------------
__global__ __launch_bounds__(256) void gemm_bias_kernel(
    const float* __restrict__ A, const float* __restrict__ B,
    const float* __restrict__ bias, float* __restrict__ C,
    int M, int N, int K)
{
    __shared__ float As[16][68];   // A^T tile: As[k][m]
    __shared__ float Bs[16][68];   // B tile:   Bs[k][n]

    const int tid = threadIdx.x;
    const int tx  = tid & 15;
    const int ty  = tid >> 4;
    const int m0  = blockIdx.y << 6;
    const int n0  = blockIdx.x << 6;

    const int ar = tid >> 2;          // 0..63  (A row in tile)
    const int ak = (tid & 3) << 2;    // 0,4,8,12 (A k-chunk)
    const int br = tid >> 4;          // 0..15  (B k-row in tile)
    const int bn = (tid & 15) << 2;   // 0..60  (B n-chunk)

    float acc[4][4];
#pragma unroll
    for (int i = 0; i < 4; i++)
#pragma unroll
        for (int j = 0; j < 4; j++) acc[i][j] = 0.0f;

    for (int k0 = 0; k0 < K; k0 += 16) {
        float4 a = *(const float4*)(A + (size_t)(m0 + ar) * K + (k0 + ak));
        float4 b = *(const float4*)(B + (size_t)(k0 + br) * N + (n0 + bn));
        As[ak + 0][ar] = a.x;
        As[ak + 1][ar] = a.y;
        As[ak + 2][ar] = a.z;
        As[ak + 3][ar] = a.w;
        *(float4*)&Bs[br][bn] = b;
        __syncthreads();

#pragma unroll
        for (int kk = 0; kk < 16; kk++) {
            float4 av = *(const float4*)&As[kk][ty << 2];
            float4 bv = *(const float4*)&Bs[kk][tx << 2];
            acc[0][0] += av.x * bv.x; acc[0][1] += av.x * bv.y;
            acc[0][2] += av.x * bv.z; acc[0][3] += av.x * bv.w;
            acc[1][0] += av.y * bv.x; acc[1][1] += av.y * bv.y;
            acc[1][2] += av.y * bv.z; acc[1][3] += av.y * bv.w;
            acc[2][0] += av.z * bv.x; acc[2][1] += av.z * bv.y;
            acc[2][2] += av.z * bv.z; acc[2][3] += av.z * bv.w;
            acc[3][0] += av.w * bv.x; acc[3][1] += av.w * bv.y;
            acc[3][2] += av.w * bv.z; acc[3][3] += av.w * bv.w;
        }
        __syncthreads();
    }

    float4 bb = *(const float4*)(bias + n0 + (tx << 2));
#pragma unroll
    for (int i = 0; i < 4; i++) {
        float4 o;
        o.x = acc[i][0] + bb.x;
        o.y = acc[i][1] + bb.y;
        o.z = acc[i][2] + bb.z;
        o.w = acc[i][3] + bb.w;
        *(float4*)(C + (size_t)(m0 + (ty << 2) + i) * N + n0 + (tx << 2)) = o;
    }
}

// ---------------------------------------------------------------------------
// Fused masked MQA attention (flash-style online softmax), fp32.
// One block = (b, h, 64-row q-tile). 256 threads (16x16), 4x4 micro-tiles.
// Shared: Qs[d][q] (Q^T), Ts[.][.] (K^T, then V), Ps[k][q] (P^T). Pad 68.
// ---------------------------------------------------------------------------
__global__ __launch_bounds__(256) void attn_kernel(const int* __restrict__ mask)
{
    extern __shared__ float sm[];
    float* Qs = sm;                  // [64][68]  Qs[d*68 + q]
    float* Ts = sm + 64 * 68;        // [64][68]  K^T: Ts[d*68+k]; later V: Ts[k*68+d]
    float* Ps = sm + 2 * 64 * 68;    // [64][68]  Ps[k*68 + q]

    const int tid = threadIdx.x;
    const int tx  = tid & 15;
    const int ty  = tid >> 4;
    const int q0  = blockIdx.x << 6;
    const int h   = blockIdx.y;
    const int b   = blockIdx.z;

    const float* Qb = g_Qp + (size_t)b * S_LEN * DM + h * DKH;
    const float* Kb = g_Kp + (size_t)b * S_LEN * DKH;
    const float* Vb = g_Vp + (size_t)b * S_LEN * DKH;
    const int*   Mb = mask + (size_t)b * S_LEN * S_LEN;

    // Load Q tile transposed: Qs[d][q]
    {
        const int r = tid >> 4;
        const int c = (tid & 15) << 2;
#pragma unroll
        for (int it = 0; it < 4; it++) {
            const int q = r + (it << 4);
            float4 v = *(const float4*)(Qb + (size_t)(q0 + q) * DM + c);
            Qs[(c + 0) * 68 + q] = v.x;
            Qs[(c + 1) * 68 + q] = v.y;
            Qs[(c + 2) * 68 + q] = v.z;
            Qs[(c + 3) * 68 + q] = v.w;
        }
    }

    float m_i[4], l_i[4], o[4][4];
#pragma unroll
    for (int i = 0; i < 4; i++) {
        m_i[i] = -3.0e38f;
        l_i[i] = 0.0f;
#pragma unroll
        for (int j = 0; j < 4; j++) o[i][j] = 0.0f;
    }

    for (int k0 = 0; k0 < S_LEN; k0 += 64) {
        __syncthreads();   // previous iteration's PV reads of Ts/Ps done; Qs visible
        // Load K tile transposed: Ts[d][k]
        {
            const int r = tid >> 4;
            const int c = (tid & 15) << 2;
#pragma unroll
            for (int it = 0; it < 4; it++) {
                const int k = r + (it << 4);
                float4 v = *(const float4*)(Kb + (size_t)(k0 + k) * DKH + c);
                Ts[(c + 0) * 68 + k] = v.x;
                Ts[(c + 1) * 68 + k] = v.y;
                Ts[(c + 2) * 68 + k] = v.z;
                Ts[(c + 3) * 68 + k] = v.w;
            }
        }
        __syncthreads();

        // S = (Q K^T): thread owns rows q0+ty*4+i, cols k0+tx*4+j
        float s[4][4];
#pragma unroll
        for (int i = 0; i < 4; i++)
#pragma unroll
            for (int j = 0; j < 4; j++) s[i][j] = 0.0f;

#pragma unroll 8
        for (int d = 0; d < 64; d++) {
            float4 av = *(const float4*)&Qs[d * 68 + (ty << 2)];
            float4 bv = *(const float4*)&Ts[d * 68 + (tx << 2)];
            s[0][0] += av.x * bv.x; s[0][1] += av.x * bv.y;
            s[0][2] += av.x * bv.z; s[0][3] += av.x * bv.w;
            s[1][0] += av.y * bv.x; s[1][1] += av.y * bv.y;
            s[1][2] += av.y * bv.z; s[1][3] += av.y * bv.w;
            s[2][0] += av.z * bv.x; s[2][1] += av.z * bv.y;
            s[2][2] += av.z * bv.z; s[2][3] += av.z * bv.w;
            s[3][0] += av.w * bv.x; s[3][1] += av.w * bv.y;
            s[3][2] += av.w * bv.z; s[3][3] += av.w * bv.w;
        }

        // scale + mask  (scores/sqrt(64) then where(mask==0, -1e9))
#pragma unroll
        for (int i = 0; i < 4; i++) {
            const int4 mk = *(const int4*)(Mb + (size_t)(q0 + (ty << 2) + i) * S_LEN
                                           + k0 + (tx << 2));
            s[i][0] = mk.x ? s[i][0] * 0.125f : -1.0e9f;
            s[i][1] = mk.y ? s[i][1] * 0.125f : -1.0e9f;
            s[i][2] = mk.z ? s[i][2] * 0.125f : -1.0e9f;
            s[i][3] = mk.w ? s[i][3] * 0.125f : -1.0e9f;
        }

        // Online softmax. Row r=ty*4+i lives on the 16 lanes sharing ty
        // (lanes [16*ty .. 16*ty+15] mod 32) -> xor-shuffles 1,2,4,8 reduce it.
#pragma unroll
        for (int i = 0; i < 4; i++) {
            float mx = fmaxf(fmaxf(s[i][0], s[i][1]), fmaxf(s[i][2], s[i][3]));
            mx = fmaxf(mx, __shfl_xor_sync(0xffffffffu, mx, 1));
            mx = fmaxf(mx, __shfl_xor_sync(0xffffffffu, mx, 2));
            mx = fmaxf(mx, __shfl_xor_sync(0xffffffffu, mx, 4));
            mx = fmaxf(mx, __shfl_xor_sync(0xffffffffu, mx, 8));
            const float mnew = fmaxf(m_i[i], mx);
            const float corr = __expf(m_i[i] - mnew);
            m_i[i] = mnew;
            float rs = 0.0f;
#pragma unroll
            for (int j = 0; j < 4; j++) {
                s[i][j] = __expf(s[i][j] - mnew);
                rs += s[i][j];
            }
            rs += __shfl_xor_sync(0xffffffffu, rs, 1);
            rs += __shfl_xor_sync(0xffffffffu, rs, 2);
            rs += __shfl_xor_sync(0xffffffffu, rs, 4);
            rs += __shfl_xor_sync(0xffffffffu, rs, 8);
            l_i[i] = l_i[i] * corr + rs;
#pragma unroll
            for (int j = 0; j < 4; j++) o[i][j] *= corr;
        }

        // Store P transposed: Ps[k][q]
#pragma unroll
        for (int j = 0; j < 4; j++)
#pragma unroll
            for (int i = 0; i < 4; i++)
                Ps[((tx << 2) + j) * 68 + (ty << 2) + i] = s[i][j];
        __syncthreads();   // all Ts(K) reads done; Ps visible

        // Load V tile (natural): Ts[k][d]
        {
            const int r = tid >> 4;
            const int c = (tid & 15) << 2;
#pragma unroll
            for (int it = 0; it < 4; it++) {
                const int k = r + (it << 4);
                *(float4*)&Ts[k * 68 + c] =
                    *(const float4*)(Vb + (size_t)(k0 + k) * DKH + c);
            }
        }
        __syncthreads();

        // O += P V : thread owns rows ty*4+i, dims tx*4+j
#pragma unroll 8
        for (int kk = 0; kk < 64; kk++) {
            float4 av = *(const float4*)&Ps[kk * 68 + (ty << 2)];
            float4 vv = *(const float4*)&Ts[kk * 68 + (tx << 2)];
            o[0][0] += av.x * vv.x; o[0][1] += av.x * vv.y;
            o[0][2] += av.x * vv.z; o[0][3] += av.x * vv.w;
            o[1][0] += av.y * vv.x; o[1][1] += av.y * vv.y;
            o[1][2] += av.y * vv.z; o[1][3] += av.y * vv.w;
            o[2][0] += av.z * vv.x; o[2][1] += av.z * vv.y;
            o[2][2] += av.z * vv.z; o[2][3] += av.z * vv.w;
            o[3][0] += av.w * vv.x; o[3][1] += av.w * vv.y;
            o[3][2] += av.w * vv.z; o[3][3] += av.w * vv.w;
        }
    }

    // Epilogue: normalize and write to g_Xo[b, q, h*64 + d]
#pragma unroll
    for (int i = 0; i < 4; i++) {
        const float inv = 1.0f / l_i[i];
        float4 r;
        r.x = o[i][0] * inv;
        r.y = o[i][1] * inv;
        r.z = o[i][2] * inv;
        r.w = o[i][3] * inv;
        *(float4*)(g_Xo + (size_t)(b * S_LEN + q0 + (ty << 2) + i) * DM
                   + h * DKH + (tx << 2)) = r;
    }
}

// ---------------------------------------------------------------------------
extern "C" void kernel_launch(void* const* d_in, const int* in_sizes, int n_in,
                              void* d_out, int out_size)
{
    const float* query = (const float*)d_in[0];
    const float* key   = (const float*)d_in[1];
    const float* value = (const float*)d_in[2];
    const int*   mask  = (const int*)  d_in[3];
    const float* Wq    = (const float*)d_in[4];
    const float* bq    = (const float*)d_in[5];
    const float* Wk    = (const float*)d_in[6];
    const float* bk    = (const float*)d_in[7];
    const float* Wv    = (const float*)d_in[8];
    const float* bv    = (const float*)d_in[9];
    const float* Wo    = (const float*)d_in[10];
    const float* bo    = (const float*)d_in[11];
    float* out = (float*)d_out;

    float *qp, *kp, *vp, *xo;
    cudaGetSymbolAddress((void**)&qp, g_Qp);
    cudaGetSymbolAddress((void**)&kp, g_Kp);
    cudaGetSymbolAddress((void**)&vp, g_Vp);
    cudaGetSymbolAddress((void**)&xo, g_Xo);

    const int attn_smem = 3 * 64 * 68 * (int)sizeof(float);  // 52224 B
    cudaFuncSetAttribute(attn_kernel,
                         cudaFuncAttributeMaxDynamicSharedMemorySize, attn_smem);

    dim3 blk(256);
    // Q projection: [4096,1024] @ [1024,1024] + bq
    gemm_bias_kernel<<<dim3(DM / 64, NTOK / 64), blk>>>(query, Wq, bq, qp, NTOK, DM, DM);
    // K projection: [4096,1024] @ [1024,64] + bk
    gemm_bias_kernel<<<dim3(DKH / 64, NTOK / 64), blk>>>(key, Wk, bk, kp, NTOK, DKH, DM);
    // V projection
    gemm_bias_kernel<<<dim3(DKH / 64, NTOK / 64), blk>>>(value, Wv, bv, vp, NTOK, DKH, DM);
    // Fused masked MQA attention
    attn_kernel<<<dim3(S_LEN / 64, NH, BATCH), blk, attn_smem>>>(mask);
    // Output projection: [4096,1024] @ [1024,1024] + bo
    gemm_bias_kernel<<<dim3(DM / 64, NTOK / 64), blk>>>(xo, Wo, bo, out, NTOK, DM, DM);
}